// round 8
// baseline (speedup 1.0000x reference)
#include <cuda_runtime.h>
#include <math.h>

#define N   384
#define NN  (384*384)
#define JQ  96
#define EA_ST 100

// ---- scratch (device globals; no allocation allowed) ----
__device__ float g_q   [256*N];
__device__ float g_Vn  [256*N];
__device__ float g_nf  [256*N];
__device__ float g_hEo [64*N];
__device__ float g_mask[N];
__device__ float g_Qk  [384*512];     // [i][e*8+h]
__device__ float g_part[384*4*528];   // per (i, quarter): m[8], s[8], T[8][64]

// ---- packed f32x2 helpers (Blackwell FFMA2) ----
__device__ __forceinline__ unsigned long long pk2(float a, float b) {
    unsigned long long d;
    asm("mov.b64 %0, {%1, %2};" : "=l"(d) : "f"(a), "f"(b));
    return d;
}
__device__ __forceinline__ unsigned long long fma2(unsigned long long a,
                                                   unsigned long long b,
                                                   unsigned long long c) {
    unsigned long long d;
    asm("fma.rn.f32x2 %0, %1, %2, %3;" : "=l"(d) : "l"(a), "l"(b), "l"(c));
    return d;
}
__device__ __forceinline__ float2 upk(unsigned long long v) {
    float2 r;
    asm("mov.b64 {%0, %1}, %2;" : "=f"(r.x), "=f"(r.y) : "l"(v));
    return r;
}
union F4U { float4 f; unsigned long long u[2]; };

// ============================================================
// Kernel 1a: q = Wq @ nodes (256 rows). grid(8,12), 256 thr.
// Block(0,0) decodes mask.
// ============================================================
__global__ __launch_bounds__(256) void k_prep_q(
    const float* __restrict__ nodes,
    const float* __restrict__ Wq,
    const unsigned int* __restrict__ maskw)
{
    __shared__ float Ws[32][33];
    __shared__ float Ns[32][36];
    __shared__ int s_flagF, s_flagB;
    int tid = threadIdx.x;

    if (blockIdx.x == 0 && blockIdx.y == 0) {
        if (tid == 0) { s_flagF = 0; s_flagB = 0; }
        __syncthreads();
        if (tid < 96) {
            unsigned v = maskw[tid];
            if (v == 0x3f800000u) atomicOr(&s_flagF, 1);   // float32 1.0
            else if (v > 1u)      atomicOr(&s_flagB, 1);   // packed u8
        }
        __syncthreads();
        bool byte_mode = (!s_flagF) && s_flagB;
        for (int j = tid; j < N; j += 256) {
            float val;
            if (byte_mode) {
                unsigned w = maskw[j >> 2];
                val = ((w >> ((j & 3) * 8)) & 0xffu) ? 1.0f : 0.0f;
            } else {
                val = maskw[j] ? 1.0f : 0.0f;
            }
            g_mask[j] = val;
        }
    }

    int r0 = blockIdx.x * 32, n0 = blockIdx.y * 32;
    int co = tid & 31, ro = (tid >> 5) * 4;
    float acc[4] = {0.f, 0.f, 0.f, 0.f};

    for (int k0 = 0; k0 < 128; k0 += 32) {
        {
            int rr = tid >> 3, kl = (tid & 7) * 4;
            float4 w = *(const float4*)(Wq + (r0 + rr) * 128 + k0 + kl);
            Ws[rr][kl+0] = w.x; Ws[rr][kl+1] = w.y;
            Ws[rr][kl+2] = w.z; Ws[rr][kl+3] = w.w;
        }
        {
            int kk = tid >> 3, cl = (tid & 7) * 4;
            float4 v = *(const float4*)(nodes + (k0 + kk) * N + n0 + cl);
            Ns[kk][cl+0] = v.x; Ns[kk][cl+1] = v.y;
            Ns[kk][cl+2] = v.z; Ns[kk][cl+3] = v.w;
        }
        __syncthreads();
        #pragma unroll
        for (int k = 0; k < 32; k++) {
            float ev = Ns[k][co];
            acc[0] = fmaf(Ws[ro+0][k], ev, acc[0]);
            acc[1] = fmaf(Ws[ro+1][k], ev, acc[1]);
            acc[2] = fmaf(Ws[ro+2][k], ev, acc[2]);
            acc[3] = fmaf(Ws[ro+3][k], ev, acc[3]);
        }
        __syncthreads();
    }
    #pragma unroll
    for (int q = 0; q < 4; q++)
        g_q[(r0 + ro + q) * N + n0 + co] = acc[q];
}

// ============================================================
// Kernel 1b: Vn = Wv[:, :128] @ nodes (256 rows). grid(8,12).
// ============================================================
__global__ __launch_bounds__(256) void k_prep_v(
    const float* __restrict__ nodes,
    const float* __restrict__ Wv)
{
    __shared__ float Ws[32][33];
    __shared__ float Ns[32][36];
    int tid = threadIdx.x;
    int r0 = blockIdx.x * 32, n0 = blockIdx.y * 32;
    int co = tid & 31, ro = (tid >> 5) * 4;
    float acc[4] = {0.f, 0.f, 0.f, 0.f};

    for (int k0 = 0; k0 < 128; k0 += 32) {
        {
            int rr = tid >> 3, kl = (tid & 7) * 4;
            float4 w = *(const float4*)(Wv + (r0 + rr) * 192 + k0 + kl);
            Ws[rr][kl+0] = w.x; Ws[rr][kl+1] = w.y;
            Ws[rr][kl+2] = w.z; Ws[rr][kl+3] = w.w;
        }
        {
            int kk = tid >> 3, cl = (tid & 7) * 4;
            float4 v = *(const float4*)(nodes + (k0 + kk) * N + n0 + cl);
            Ns[kk][cl+0] = v.x; Ns[kk][cl+1] = v.y;
            Ns[kk][cl+2] = v.z; Ns[kk][cl+3] = v.w;
        }
        __syncthreads();
        #pragma unroll
        for (int k = 0; k < 32; k++) {
            float ev = Ns[k][co];
            acc[0] = fmaf(Ws[ro+0][k], ev, acc[0]);
            acc[1] = fmaf(Ws[ro+1][k], ev, acc[1]);
            acc[2] = fmaf(Ws[ro+2][k], ev, acc[2]);
            acc[3] = fmaf(Ws[ro+3][k], ev, acc[3]);
        }
        __syncthreads();
    }
    #pragma unroll
    for (int q = 0; q < 4; q++)
        g_Vn[(r0 + ro + q) * N + n0 + co] = acc[q];
}

// ============================================================
// Kernel 1c: Qk[i][e*8+h] = rs * sum_a q[h*32+a, i] * Wk[h*32+a][128+e]
// grid(12) = 32 i per CTA, 256 thr.
// ============================================================
__global__ __launch_bounds__(256) void k_qk(const float* __restrict__ Wk)
{
    __shared__ float qs[256 * 36];   // [r][ii], stride 36 (16B aligned)
    __shared__ float wks[32 * 68];   // [a][e]
    int tid = threadIdx.x;
    int i0 = blockIdx.x * 32;
    const float rs = 0.17677669529663687f;

    #pragma unroll
    for (int it = 0; it < 32; it++) {
        int idx = it * 256 + tid;
        int r = idx >> 5, ii = idx & 31;
        qs[r * 36 + ii] = g_q[r * N + i0 + ii];
    }

    int e = tid & 63, ig = tid >> 6;
    for (int h = 0; h < 8; h++) {
        __syncthreads();
        #pragma unroll
        for (int it = 0; it < 8; it++) {
            int idx = it * 256 + tid;
            int a = idx >> 6, ee = idx & 63;
            wks[a * 68 + ee] = Wk[(h * 32 + a) * 192 + 128 + ee];
        }
        __syncthreads();
        float acc[8] = {0.f,0.f,0.f,0.f,0.f,0.f,0.f,0.f};
        #pragma unroll
        for (int a = 0; a < 32; a++) {
            float w = wks[a * 68 + e];
            const float* qr = qs + (h * 32 + a) * 36 + ig * 8;
            float4 qa = *(const float4*)qr;
            float4 qb = *(const float4*)(qr + 4);
            acc[0] = fmaf(w, qa.x, acc[0]); acc[1] = fmaf(w, qa.y, acc[1]);
            acc[2] = fmaf(w, qa.z, acc[2]); acc[3] = fmaf(w, qa.w, acc[3]);
            acc[4] = fmaf(w, qb.x, acc[4]); acc[5] = fmaf(w, qb.y, acc[5]);
            acc[6] = fmaf(w, qb.z, acc[6]); acc[7] = fmaf(w, qb.w, acc[7]);
        }
        #pragma unroll
        for (int ii = 0; ii < 8; ii++)
            g_Qk[(size_t)(i0 + ig * 8 + ii) * 512 + e * 8 + h] = rs * acc[ii];
    }
}

// ============================================================
// Kernel 2a: attention partials. grid(1536) = 384 i x 4 quarters.
// LAUNCH SLOT #4 (ncu-visible). 256 thr, ~35KB smem.
// ============================================================
__global__ __launch_bounds__(256) void k_attnA(const float* __restrict__ edges)
{
    __shared__ float Es[64 * EA_ST];
    __shared__ float s_p[JQ * 12];
    __shared__ float s_Qk[512];
    __shared__ float s_T[512];
    __shared__ float s_ms[16];
    __shared__ float s_mf[JQ];

    int bx = blockIdx.x;
    int i = bx >> 2, qn = bx & 3, jb = qn * JQ;
    int tid = threadIdx.x, lane = tid & 31, wid = tid >> 5;

    s_Qk[tid]       = g_Qk[(size_t)i * 512 + tid];
    s_Qk[256 + tid] = g_Qk[(size_t)i * 512 + 256 + tid];
    if (tid < JQ) s_mf[tid] = g_mask[jb + tid];

    // stage edges[e, i, jb..jb+95]
    const float* erow = edges + (size_t)i * N + jb;
    #pragma unroll
    for (int it = 0; it < 6; it++) {
        int idx = it * 256 + tid;
        int e = idx / 24, c4 = idx - e * 24;
        float4 v = *(const float4*)(erow + (size_t)e * NN + c4 * 4);
        *(float4*)&Es[e * EA_ST + c4 * 4] = v;
    }
    __syncthreads();

    // pass 1: sim for local quarter. thread = (jloc, h-half). 192 items.
    if (tid < 2 * JQ) {
        int jloc = tid >> 1, hh = tid & 1;
        unsigned long long acc2[2] = {0ull, 0ull};
        const float* ep = Es + jloc;
        const float* qp = s_Qk + hh * 4;
        #pragma unroll 8
        for (int e = 0; e < 64; e++) {
            float ev = ep[e * EA_ST];
            unsigned long long evd = pk2(ev, ev);
            F4U q; q.f = *(const float4*)(qp + e * 8);
            acc2[0] = fma2(q.u[0], evd, acc2[0]);
            acc2[1] = fma2(q.u[1], evd, acc2[1]);
        }
        F4U o;
        if (s_mf[jloc] > 0.f) {
            float2 a = upk(acc2[0]), b = upk(acc2[1]);
            o.f = make_float4(a.x, a.y, b.x, b.y);
        } else {
            o.f = make_float4(-INFINITY, -INFINITY, -INFINITY, -INFINITY);
        }
        *(float4*)&s_p[jloc * 12 + hh * 4] = o.f;
    }
    __syncthreads();

    // local softmax stats per head; s_p <- raw exp(sim - m_local)
    if (wid < 8) {
        int h = wid;
        float m = -INFINITY;
        #pragma unroll
        for (int jl = lane; jl < JQ; jl += 32) m = fmaxf(m, s_p[jl * 12 + h]);
        #pragma unroll
        for (int o = 16; o; o >>= 1) m = fmaxf(m, __shfl_xor_sync(0xffffffffu, m, o));
        float mexp = (m == -INFINITY) ? 0.f : m;
        float sum = 0.f;
        #pragma unroll
        for (int jl = lane; jl < JQ; jl += 32) {
            float ev = __expf(s_p[jl * 12 + h] - mexp);
            s_p[jl * 12 + h] = ev;
            sum += ev;
        }
        #pragma unroll
        for (int o = 16; o; o >>= 1) sum += __shfl_xor_sync(0xffffffffu, sum, o);
        if (lane == 0) { s_ms[h] = m; s_ms[8 + h] = sum; }
    }
    __syncthreads();

    // raw partial T over local quarter
    #pragma unroll 1
    for (int k = 0; k < 8; k++) {
        int e = wid + k * 8;
        const float* ep = Es + e * EA_ST;
        unsigned long long acc2[4] = {0ull, 0ull, 0ull, 0ull};
        #pragma unroll
        for (int jl = lane; jl < JQ; jl += 32) {
            float ev = ep[jl];
            unsigned long long evd = pk2(ev, ev);
            F4U p0; p0.f = *(const float4*)&s_p[jl * 12];
            F4U p1; p1.f = *(const float4*)&s_p[jl * 12 + 4];
            acc2[0] = fma2(p0.u[0], evd, acc2[0]);
            acc2[1] = fma2(p0.u[1], evd, acc2[1]);
            acc2[2] = fma2(p1.u[0], evd, acc2[2]);
            acc2[3] = fma2(p1.u[1], evd, acc2[3]);
        }
        #pragma unroll
        for (int hp = 0; hp < 4; hp++) {
            float2 v = upk(acc2[hp]);
            #pragma unroll
            for (int o = 16; o; o >>= 1) {
                v.x += __shfl_xor_sync(0xffffffffu, v.x, o);
                v.y += __shfl_xor_sync(0xffffffffu, v.y, o);
            }
            if (lane == 0) {
                s_T[(2 * hp)     * 64 + e] = v.x;
                s_T[(2 * hp + 1) * 64 + e] = v.y;
            }
        }
    }
    __syncthreads();

    float* gp = g_part + ((size_t)i * 4 + qn) * 528;
    if (tid < 16) gp[tid] = s_ms[tid];
    #pragma unroll
    for (int r = 0; r < 2; r++) {
        int idx = r * 256 + tid;
        gp[16 + idx] = s_T[idx];
    }
}

// ============================================================
// Kernel 2b: combine quarters -> node_features. grid(384), 256 thr.
// ============================================================
__global__ __launch_bounds__(256) void k_attnB(const float* __restrict__ Wv)
{
    __shared__ float s_T[512];
    __shared__ float s_fac[32];
    int i = blockIdx.x;
    int tid = threadIdx.x;
    float maski = g_mask[i];
    const float* gp = g_part + (size_t)i * 4 * 528;

    if (tid < 32) {
        int q = tid >> 3, h = tid & 7;
        float m = gp[q * 528 + h];
        float s = gp[q * 528 + 8 + h];
        float mg = m;
        mg = fmaxf(mg, __shfl_xor_sync(0xffffffffu, mg, 8));
        mg = fmaxf(mg, __shfl_xor_sync(0xffffffffu, mg, 16));
        float mg2 = (mg == -INFINITY) ? 0.f : mg;
        float w = s * __expf(m - mg2);
        float tot = w;
        tot += __shfl_xor_sync(0xffffffffu, tot, 8);
        tot += __shfl_xor_sync(0xffffffffu, tot, 16);
        s_fac[q * 8 + h] = __expf(m - mg2) * maski / tot;
    }
    __syncthreads();

    #pragma unroll
    for (int r = 0; r < 2; r++) {
        int idx = r * 256 + tid;
        int h = idx >> 6;
        float acc = 0.f;
        #pragma unroll
        for (int q = 0; q < 4; q++)
            acc = fmaf(s_fac[q * 8 + h], gp[q * 528 + 16 + idx], acc);
        s_T[idx] = acc;
    }
    __syncthreads();

    {
        int hv = tid, h = hv >> 5;
        const float* wvp = Wv + hv * 192 + 128;
        float acc = g_Vn[hv * N + i] * maski;
        #pragma unroll
        for (int e = 0; e < 64; e++) acc = fmaf(wvp[e], s_T[h * 64 + e], acc);
        g_nf[hv * N + i] = acc;
    }
}

// ============================================================
// Kernel 3: node_out = Wo@nf ; hEo = 0.5*We[:,:256]@nf
// grid(6,12), 256 thr, tile 32x32, double-buffered K loop.
// ============================================================
__global__ __launch_bounds__(256) void k_post(
    const float* __restrict__ Wo,
    const float* __restrict__ We,
    float* __restrict__ out)
{
    __shared__ float Ws[32][33];
    __shared__ float Ns[32][36];
    int tid = threadIdx.x;
    int r0 = blockIdx.x * 32, n0 = blockIdx.y * 32;
    int co = tid & 31, ro = (tid >> 5) * 4;
    float acc[4] = {0.f, 0.f, 0.f, 0.f};

    int rr = tid >> 3, kl = (tid & 7) * 4;
    int kk = tid >> 3, cl = (tid & 7) * 4;
    int r = r0 + rr;
    const float* wp = (r < 128) ? (Wo + r * 256) : (We + (r - 128) * 320);

    float4 wreg = *(const float4*)(wp + kl);
    float4 nreg = *(const float4*)(g_nf + kk * N + n0 + cl);

    for (int k0 = 0; k0 < 256; k0 += 32) {
        Ws[rr][kl+0] = wreg.x; Ws[rr][kl+1] = wreg.y;
        Ws[rr][kl+2] = wreg.z; Ws[rr][kl+3] = wreg.w;
        Ns[kk][cl+0] = nreg.x; Ns[kk][cl+1] = nreg.y;
        Ns[kk][cl+2] = nreg.z; Ns[kk][cl+3] = nreg.w;
        __syncthreads();
        if (k0 < 224) {
            wreg = *(const float4*)(wp + k0 + 32 + kl);
            nreg = *(const float4*)(g_nf + (k0 + 32 + kk) * N + n0 + cl);
        }
        #pragma unroll
        for (int k = 0; k < 32; k++) {
            float ev = Ns[k][co];
            acc[0] = fmaf(Ws[ro+0][k], ev, acc[0]);
            acc[1] = fmaf(Ws[ro+1][k], ev, acc[1]);
            acc[2] = fmaf(Ws[ro+2][k], ev, acc[2]);
            acc[3] = fmaf(Ws[ro+3][k], ev, acc[3]);
        }
        __syncthreads();
    }
    #pragma unroll
    for (int q = 0; q < 4; q++) {
        int rq = r0 + ro + q;
        if (rq < 128) out[rq * N + n0 + co] = acc[q];
        else          g_hEo[(rq - 128) * N + n0 + co] = 0.5f * acc[q];
    }
}

// ============================================================
// Kernel 4: edge_out. grid(768), 256 thr, 3 CTAs/SM (~68KB smem).
// CTA tile 64o x 192c; thread tile 8o x 6c (4 + 2 split).
// ============================================================
#define EG_ST 196
#define EDGE_SMEM ((64*68 + 64*EG_ST) * 4)

__global__ __launch_bounds__(256, 3) void k_edge(
    const float* __restrict__ edges,
    const float* __restrict__ We,
    float* __restrict__ out)
{
    extern __shared__ float esm[];
    float* Ws = esm;              // [64][68]  Ws[e][o]
    float* Es = esm + 64 * 68;    // [64][196]

    int tid = threadIdx.x, lane = tid & 31, wid = tid >> 5;
    int b = blockIdx.x;
    int i = b >> 1, jb = (b & 1) * 192;
    size_t cbase = (size_t)b * 192;

    {
        int o = tid >> 2, e0 = (tid & 3) * 16;
        const float* wp = We + o * 320 + 256 + e0;
        #pragma unroll
        for (int u = 0; u < 16; u += 4) {
            float4 w = *(const float4*)(wp + u);
            Ws[(e0+u+0)*68 + o] = w.x; Ws[(e0+u+1)*68 + o] = w.y;
            Ws[(e0+u+2)*68 + o] = w.z; Ws[(e0+u+3)*68 + o] = w.w;
        }
    }
    #pragma unroll
    for (int it = 0; it < 12; it++) {
        int idx = it * 256 + tid;
        int e = idx / 48, c4 = idx - e * 48;
        float4 v = *(const float4*)(edges + (size_t)e * NN + cbase + c4 * 4);
        *(float4*)&Es[e * EG_ST + c4 * 4] = v;
    }
    __syncthreads();

    int o0 = wid * 8;
    unsigned long long acc2[4][6];
    #pragma unroll
    for (int op = 0; op < 4; op++)
        #pragma unroll
        for (int p = 0; p < 6; p++) acc2[op][p] = 0ull;

    #pragma unroll 4
    for (int e = 0; e < 64; e++) {
        const float* wr = Ws + e * 68 + o0;
        F4U w0; w0.f = *(const float4*)wr;
        F4U w1; w1.f = *(const float4*)(wr + 4);
        unsigned long long wd[4] = { w0.u[0], w0.u[1], w1.u[0], w1.u[1] };
        const float* er = Es + e * EG_ST;
        float4 ea = *(const float4*)(er + lane * 4);
        float2 eb = *(const float2*)(er + 128 + lane * 2);
        float ev[6] = { ea.x, ea.y, ea.z, ea.w, eb.x, eb.y };
        #pragma unroll
        for (int p = 0; p < 6; p++) {
            unsigned long long evd = pk2(ev[p], ev[p]);
            acc2[0][p] = fma2(wd[0], evd, acc2[0][p]);
            acc2[1][p] = fma2(wd[1], evd, acc2[1][p]);
            acc2[2][p] = fma2(wd[2], evd, acc2[2][p]);
            acc2[3][p] = fma2(wd[3], evd, acc2[3][p]);
        }
    }

    float* ob = out + 128 * N;
    int j0 = jb + lane * 4;
    int j1 = jb + 128 + lane * 2;
    #pragma unroll
    for (int op = 0; op < 4; op++) {
        int oA = o0 + 2 * op, oB = oA + 1;
        float eoiA = g_hEo[oA * N + i];
        float eoiB = g_hEo[oB * N + i];
        float4 ejA = *(const float4*)(g_hEo + oA * N + j0);
        float4 ejB = *(const float4*)(g_hEo + oB * N + j0);
        float2 fjA = *(const float2*)(g_hEo + oA * N + j1);
        float2 fjB = *(const float2*)(g_hEo + oB * N + j1);
        float2 v0 = upk(acc2[op][0]);
        float2 v1 = upk(acc2[op][1]);
        float2 v2 = upk(acc2[op][2]);
        float2 v3 = upk(acc2[op][3]);
        float2 v4 = upk(acc2[op][4]);
        float2 v5 = upk(acc2[op][5]);
        float* pA = ob + (size_t)oA * NN + (size_t)i * N;
        float* pB = ob + (size_t)oB * NN + (size_t)i * N;
        *(float4*)(pA + j0) = make_float4(v0.x + eoiA + ejA.x, v1.x + eoiA + ejA.y,
                                          v2.x + eoiA + ejA.z, v3.x + eoiA + ejA.w);
        *(float4*)(pB + j0) = make_float4(v0.y + eoiB + ejB.x, v1.y + eoiB + ejB.y,
                                          v2.y + eoiB + ejB.z, v3.y + eoiB + ejB.w);
        *(float2*)(pA + j1) = make_float2(v4.x + eoiA + fjA.x, v5.x + eoiA + fjA.y);
        *(float2*)(pB + j1) = make_float2(v4.y + eoiB + fjB.x, v5.y + eoiB + fjB.y);
    }
}

// ============================================================
extern "C" void kernel_launch(void* const* d_in, const int* in_sizes, int n_in,
                              void* d_out, int out_size)
{
    const float* nodes = (const float*)d_in[0];
    const float* edges = (const float*)d_in[1];
    const unsigned int* mask = (const unsigned int*)d_in[2];
    const float* Wq = (const float*)d_in[3];
    const float* Wk = (const float*)d_in[4];
    const float* Wv = (const float*)d_in[5];
    const float* Wo = (const float*)d_in[6];
    const float* We = (const float*)d_in[7];
    float* out = (float*)d_out;

    cudaFuncSetAttribute(k_edge, cudaFuncAttributeMaxDynamicSharedMemorySize, EDGE_SMEM);

    k_prep_q<<<dim3(8, 12), 256>>>(nodes, Wq, mask);   // #1
    k_prep_v<<<dim3(8, 12), 256>>>(nodes, Wv);         // #2
    k_qk<<<12, 256>>>(Wk);                             // #3
    k_attnA<<<1536, 256>>>(edges);                     // #4  <- ncu slot
    k_attnB<<<384, 256>>>(Wv);                         // #5
    k_post<<<dim3(6, 12), 256>>>(Wo, We, out);         // #6
    k_edge<<<768, 256, EDGE_SMEM>>>(edges, We, out);   // #7
}

// round 9
// speedup vs baseline: 1.3239x; 1.3239x over previous
#include <cuda_runtime.h>
#include <math.h>

#define N   384
#define NN  (384*384)
#define JH  192

// ---- scratch (device globals; no allocation allowed) ----
__device__ float g_q   [256*N];
__device__ float g_Vn  [256*N];
__device__ float g_nf  [256*N];
__device__ float g_hEo [64*N];
__device__ float g_mask[N];
__device__ float g_Qk  [384*512];     // [i][e*8+h]
__device__ float g_part[384*2*528];   // per (i, half): m[8], s[8], T[8][64]

// ---- packed f32x2 helpers (Blackwell FFMA2) ----
__device__ __forceinline__ unsigned long long pk2(float a, float b) {
    unsigned long long d;
    asm("mov.b64 %0, {%1, %2};" : "=l"(d) : "f"(a), "f"(b));
    return d;
}
__device__ __forceinline__ unsigned long long fma2(unsigned long long a,
                                                   unsigned long long b,
                                                   unsigned long long c) {
    unsigned long long d;
    asm("fma.rn.f32x2 %0, %1, %2, %3;" : "=l"(d) : "l"(a), "l"(b), "l"(c));
    return d;
}
__device__ __forceinline__ float2 upk(unsigned long long v) {
    float2 r;
    asm("mov.b64 {%0, %1}, %2;" : "=f"(r.x), "=f"(r.y) : "l"(v));
    return r;
}
union F4U { float4 f; unsigned long long u[2]; };

// ============================================================
// Kernel 1a: q = Wq @ nodes (256 rows). grid(8,12), 256 thr.
// Block(0,0) decodes mask (parallel mode detect).
// ============================================================
__global__ __launch_bounds__(256) void k_prep_q(
    const float* __restrict__ nodes,
    const float* __restrict__ Wq,
    const unsigned int* __restrict__ maskw)
{
    __shared__ float Ws[32][33];
    __shared__ float Ns[32][36];
    __shared__ int s_flagF, s_flagB;
    int tid = threadIdx.x;

    if (blockIdx.x == 0 && blockIdx.y == 0) {
        if (tid == 0) { s_flagF = 0; s_flagB = 0; }
        __syncthreads();
        if (tid < 96) {
            unsigned v = maskw[tid];
            if (v == 0x3f800000u) atomicOr(&s_flagF, 1);
            else if (v > 1u)      atomicOr(&s_flagB, 1);
        }
        __syncthreads();
        bool byte_mode = (!s_flagF) && s_flagB;
        for (int j = tid; j < N; j += 256) {
            float val;
            if (byte_mode) {
                unsigned w = maskw[j >> 2];
                val = ((w >> ((j & 3) * 8)) & 0xffu) ? 1.0f : 0.0f;
            } else {
                val = maskw[j] ? 1.0f : 0.0f;
            }
            g_mask[j] = val;
        }
    }

    int r0 = blockIdx.x * 32, n0 = blockIdx.y * 32;
    int co = tid & 31, ro = (tid >> 5) * 4;
    float acc[4] = {0.f, 0.f, 0.f, 0.f};

    for (int k0 = 0; k0 < 128; k0 += 32) {
        {
            int rr = tid >> 3, kl = (tid & 7) * 4;
            float4 w = *(const float4*)(Wq + (r0 + rr) * 128 + k0 + kl);
            Ws[rr][kl+0] = w.x; Ws[rr][kl+1] = w.y;
            Ws[rr][kl+2] = w.z; Ws[rr][kl+3] = w.w;
        }
        {
            int kk = tid >> 3, cl = (tid & 7) * 4;
            float4 v = *(const float4*)(nodes + (k0 + kk) * N + n0 + cl);
            Ns[kk][cl+0] = v.x; Ns[kk][cl+1] = v.y;
            Ns[kk][cl+2] = v.z; Ns[kk][cl+3] = v.w;
        }
        __syncthreads();
        #pragma unroll
        for (int k = 0; k < 32; k++) {
            float ev = Ns[k][co];
            acc[0] = fmaf(Ws[ro+0][k], ev, acc[0]);
            acc[1] = fmaf(Ws[ro+1][k], ev, acc[1]);
            acc[2] = fmaf(Ws[ro+2][k], ev, acc[2]);
            acc[3] = fmaf(Ws[ro+3][k], ev, acc[3]);
        }
        __syncthreads();
    }
    #pragma unroll
    for (int q = 0; q < 4; q++)
        g_q[(r0 + ro + q) * N + n0 + co] = acc[q];
}

// ============================================================
// Kernel 1b: Vn = Wv[:, :128] @ nodes (256 rows). grid(8,12).
// ============================================================
__global__ __launch_bounds__(256) void k_prep_v(
    const float* __restrict__ nodes,
    const float* __restrict__ Wv)
{
    __shared__ float Ws[32][33];
    __shared__ float Ns[32][36];
    int tid = threadIdx.x;
    int r0 = blockIdx.x * 32, n0 = blockIdx.y * 32;
    int co = tid & 31, ro = (tid >> 5) * 4;
    float acc[4] = {0.f, 0.f, 0.f, 0.f};

    for (int k0 = 0; k0 < 128; k0 += 32) {
        {
            int rr = tid >> 3, kl = (tid & 7) * 4;
            float4 w = *(const float4*)(Wv + (r0 + rr) * 192 + k0 + kl);
            Ws[rr][kl+0] = w.x; Ws[rr][kl+1] = w.y;
            Ws[rr][kl+2] = w.z; Ws[rr][kl+3] = w.w;
        }
        {
            int kk = tid >> 3, cl = (tid & 7) * 4;
            float4 v = *(const float4*)(nodes + (k0 + kk) * N + n0 + cl);
            Ns[kk][cl+0] = v.x; Ns[kk][cl+1] = v.y;
            Ns[kk][cl+2] = v.z; Ns[kk][cl+3] = v.w;
        }
        __syncthreads();
        #pragma unroll
        for (int k = 0; k < 32; k++) {
            float ev = Ns[k][co];
            acc[0] = fmaf(Ws[ro+0][k], ev, acc[0]);
            acc[1] = fmaf(Ws[ro+1][k], ev, acc[1]);
            acc[2] = fmaf(Ws[ro+2][k], ev, acc[2]);
            acc[3] = fmaf(Ws[ro+3][k], ev, acc[3]);
        }
        __syncthreads();
    }
    #pragma unroll
    for (int q = 0; q < 4; q++)
        g_Vn[(r0 + ro + q) * N + n0 + co] = acc[q];
}

// ============================================================
// Kernel 1c: Qk. grid(48, 8) = (8 i per CTA, h). 256 thr.
// ============================================================
__global__ __launch_bounds__(256) void k_qk(const float* __restrict__ Wk)
{
    __shared__ float qs[32 * 8];     // [a][ii]
    __shared__ float wks[32 * 68];   // [a][e]
    int tid = threadIdx.x;
    int i0 = blockIdx.x * 8, h = blockIdx.y;
    const float rs = 0.17677669529663687f;

    qs[tid] = g_q[(h * 32 + (tid >> 3)) * N + i0 + (tid & 7)];
    #pragma unroll
    for (int it = 0; it < 8; it++) {
        int idx = it * 256 + tid;
        int a = idx >> 6, e = idx & 63;
        wks[a * 68 + e] = Wk[(h * 32 + a) * 192 + 128 + e];
    }
    __syncthreads();

    int e = tid & 63, ig = tid >> 6;
    float acc0 = 0.f, acc1 = 0.f;
    #pragma unroll
    for (int a = 0; a < 32; a++) {
        float w = wks[a * 68 + e];
        float2 q2 = *(const float2*)&qs[a * 8 + ig * 2];
        acc0 = fmaf(w, q2.x, acc0);
        acc1 = fmaf(w, q2.y, acc1);
    }
    g_Qk[(size_t)(i0 + ig * 2 + 0) * 512 + e * 8 + h] = rs * acc0;
    g_Qk[(size_t)(i0 + ig * 2 + 1) * 512 + e * 8 + h] = rs * acc1;
}

// ============================================================
// Kernel 2a: attention partials. grid(768) = 384 i x 2 halves.
// 256 thr, ~66KB dyn smem (3 CTAs/SM). LAUNCH SLOT #4.
// Wavefront-optimized LDS: pass1 (2j x 4h tiles), pass2 each
// thread owns one (e, h-pair) output (no shuffle reductions).
// ============================================================
#define ES_ST 196
#define PH_ST 200
#define P2W   392
#define ATTN_FLOATS (64*ES_ST + 8*PH_ST + 4*P2W + 512 + 192 + 16)
#define ATTN_SMEM (ATTN_FLOATS * 4)

__global__ __launch_bounds__(256) void k_attnA(const float* __restrict__ edges)
{
    extern __shared__ float sm[];
    float* Es   = sm;                      // [64][196]
    float* s_ph = Es + 64 * ES_ST;         // [8][200]  sim -> raw exp
    float* p2f  = s_ph + 8 * PH_ST;        // [4][392]  h-pair float2 rows
    float* s_Qk = p2f + 4 * P2W;           // [64][8]
    float* s_mf = s_Qk + 512;              // [192]
    float* s_ms = s_mf + 192;              // [16]

    int bx = blockIdx.x;
    int i = bx >> 1, half = bx & 1, jb = half * JH;
    int tid = threadIdx.x, lane = tid & 31, wid = tid >> 5;

    s_Qk[tid]       = g_Qk[(size_t)i * 512 + tid];
    s_Qk[256 + tid] = g_Qk[(size_t)i * 512 + 256 + tid];
    if (tid < JH) s_mf[tid] = g_mask[jb + tid];

    // stage edges[e, i, jb..jb+191]: 64 x 48 float4 = 3072 / 256 = 12 each
    const float* erow = edges + (size_t)i * N + jb;
    #pragma unroll
    for (int it = 0; it < 12; it++) {
        int idx = it * 256 + tid;
        int e = idx / 48, c4 = idx - e * 48;
        float4 v = *(const float4*)(erow + (size_t)e * NN + c4 * 4);
        *(float4*)&Es[e * ES_ST + c4 * 4] = v;
    }
    __syncthreads();

    // pass 1: sim. thread = (jg of 96, hh of 2). 192 active threads.
    if (tid < 192) {
        int jg = tid >> 1, hh = tid & 1;
        int j0 = jg * 2;
        unsigned long long acc2[4] = {0ull, 0ull, 0ull, 0ull};
        const float* ep = Es + j0;
        const float* qp = s_Qk + hh * 4;
        #pragma unroll 8
        for (int e = 0; e < 64; e++) {
            float2 ev = *(const float2*)(ep + e * ES_ST);
            unsigned long long ed0 = pk2(ev.x, ev.x);
            unsigned long long ed1 = pk2(ev.y, ev.y);
            F4U q; q.f = *(const float4*)(qp + e * 8);
            acc2[0] = fma2(q.u[0], ed0, acc2[0]);
            acc2[1] = fma2(q.u[1], ed0, acc2[1]);
            acc2[2] = fma2(q.u[0], ed1, acc2[2]);
            acc2[3] = fma2(q.u[1], ed1, acc2[3]);
        }
        float m0 = (s_mf[j0]     > 0.f) ? 0.f : 1.f;
        float m1 = (s_mf[j0 + 1] > 0.f) ? 0.f : 1.f;
        float2 a0 = upk(acc2[0]), a1 = upk(acc2[1]);
        float2 b0 = upk(acc2[2]), b1 = upk(acc2[3]);
        int hb = hh * 4;
        s_ph[(hb+0)*PH_ST + j0] = m0 ? -INFINITY : a0.x;
        s_ph[(hb+1)*PH_ST + j0] = m0 ? -INFINITY : a0.y;
        s_ph[(hb+2)*PH_ST + j0] = m0 ? -INFINITY : a1.x;
        s_ph[(hb+3)*PH_ST + j0] = m0 ? -INFINITY : a1.y;
        s_ph[(hb+0)*PH_ST + j0+1] = m1 ? -INFINITY : b0.x;
        s_ph[(hb+1)*PH_ST + j0+1] = m1 ? -INFINITY : b0.y;
        s_ph[(hb+2)*PH_ST + j0+1] = m1 ? -INFINITY : b1.x;
        s_ph[(hb+3)*PH_ST + j0+1] = m1 ? -INFINITY : b1.y;
    }
    __syncthreads();

    // local softmax stats: warp h owns row h ([h][j] contiguous)
    {
        int h = wid;
        float* row = s_ph + h * PH_ST;
        float m = -INFINITY;
        #pragma unroll
        for (int jl = lane; jl < JH; jl += 32) m = fmaxf(m, row[jl]);
        #pragma unroll
        for (int o = 16; o; o >>= 1) m = fmaxf(m, __shfl_xor_sync(0xffffffffu, m, o));
        float mexp = (m == -INFINITY) ? 0.f : m;
        float sum = 0.f;
        #pragma unroll
        for (int jl = lane; jl < JH; jl += 32) {
            float ev = __expf(row[jl] - mexp);
            row[jl] = ev;
            sum += ev;
        }
        #pragma unroll
        for (int o = 16; o; o >>= 1) sum += __shfl_xor_sync(0xffffffffu, sum, o);
        if (lane == 0) { s_ms[h] = m; s_ms[8 + h] = sum; }
    }
    __syncthreads();

    // repack raw exp into h-pair float2 rows: p2f[hp][2j] = (p[2hp][j], p[2hp+1][j])
    #pragma unroll
    for (int k = 0; k < 3; k++) {
        int idx = k * 256 + tid;           // 768 = 4 hp * 192 j
        int hp = idx / JH, j = idx - hp * JH;
        float x = s_ph[(2*hp)   * PH_ST + j];
        float y = s_ph[(2*hp+1) * PH_ST + j];
        *(float2*)&p2f[hp * P2W + 2*j] = make_float2(x, y);
    }
    __syncthreads();

    // pass 2: T[2hp..2hp+1][e] owned entirely by thread (e, hp)
    float* gp = g_part + ((size_t)i * 2 + half) * 528;
    {
        int e = tid >> 2, hp = tid & 3;
        const float* ep = Es + e * ES_ST;
        const float* pp = p2f + hp * P2W;
        unsigned long long acc2[4] = {0ull, 0ull, 0ull, 0ull};
        #pragma unroll 6
        for (int j = 0; j < JH; j += 4) {
            float4 ev4 = *(const float4*)(ep + j);
            F4U pA; pA.f = *(const float4*)(pp + 2*j);
            F4U pB; pB.f = *(const float4*)(pp + 2*j + 4);
            acc2[0] = fma2(pA.u[0], pk2(ev4.x, ev4.x), acc2[0]);
            acc2[1] = fma2(pA.u[1], pk2(ev4.y, ev4.y), acc2[1]);
            acc2[2] = fma2(pB.u[0], pk2(ev4.z, ev4.z), acc2[2]);
            acc2[3] = fma2(pB.u[1], pk2(ev4.w, ev4.w), acc2[3]);
        }
        float2 t0 = upk(acc2[0]), t1 = upk(acc2[1]);
        float2 t2 = upk(acc2[2]), t3 = upk(acc2[3]);
        float tx = (t0.x + t1.x) + (t2.x + t3.x);
        float ty = (t0.y + t1.y) + (t2.y + t3.y);
        gp[16 + (2*hp)   * 64 + e] = tx;
        gp[16 + (2*hp+1) * 64 + e] = ty;
    }
    if (tid < 16) gp[tid] = s_ms[tid];
}

// ============================================================
// Kernel 2b: combine halves -> node_features. grid(384), 256 thr.
// ============================================================
__global__ __launch_bounds__(256) void k_attnB(const float* __restrict__ Wv)
{
    __shared__ float s_T[512];
    __shared__ float s_fac[16];
    int i = blockIdx.x;
    int tid = threadIdx.x;
    float maski = g_mask[i];
    const float* gp = g_part + (size_t)i * 2 * 528;

    if (tid < 16) {
        int q = tid >> 3, h = tid & 7;
        float m = gp[q * 528 + h];
        float s = gp[q * 528 + 8 + h];
        float mo = __shfl_xor_sync(0xffffu, m, 8);
        float mg = fmaxf(m, mo);
        float mg2 = (mg == -INFINITY) ? 0.f : mg;
        float w = s * __expf(m - mg2);
        float tot = w + __shfl_xor_sync(0xffffu, w, 8);
        s_fac[q * 8 + h] = __expf(m - mg2) * maski / tot;
    }
    __syncthreads();

    #pragma unroll
    for (int r = 0; r < 2; r++) {
        int idx = r * 256 + tid;
        int h = idx >> 6;
        s_T[idx] = s_fac[h] * gp[16 + idx] + s_fac[8 + h] * gp[528 + 16 + idx];
    }
    __syncthreads();

    {
        int hv = tid, h = hv >> 5;
        const float* wvp = Wv + hv * 192 + 128;
        float acc = g_Vn[hv * N + i] * maski;
        #pragma unroll
        for (int e = 0; e < 64; e++) acc = fmaf(wvp[e], s_T[h * 64 + e], acc);
        g_nf[hv * N + i] = acc;
    }
}

// ============================================================
// Kernel 3: node_out = Wo@nf ; hEo = 0.5*We[:,:256]@nf
// grid(6,12), 256 thr, tile 32x32, double-buffered K loop.
// ============================================================
__global__ __launch_bounds__(256) void k_post(
    const float* __restrict__ Wo,
    const float* __restrict__ We,
    float* __restrict__ out)
{
    __shared__ float Ws[32][33];
    __shared__ float Ns[32][36];
    int tid = threadIdx.x;
    int r0 = blockIdx.x * 32, n0 = blockIdx.y * 32;
    int co = tid & 31, ro = (tid >> 5) * 4;
    float acc[4] = {0.f, 0.f, 0.f, 0.f};

    int rr = tid >> 3, kl = (tid & 7) * 4;
    int kk = tid >> 3, cl = (tid & 7) * 4;
    int r = r0 + rr;
    const float* wp = (r < 128) ? (Wo + r * 256) : (We + (r - 128) * 320);

    float4 wreg = *(const float4*)(wp + kl);
    float4 nreg = *(const float4*)(g_nf + kk * N + n0 + cl);

    for (int k0 = 0; k0 < 256; k0 += 32) {
        Ws[rr][kl+0] = wreg.x; Ws[rr][kl+1] = wreg.y;
        Ws[rr][kl+2] = wreg.z; Ws[rr][kl+3] = wreg.w;
        Ns[kk][cl+0] = nreg.x; Ns[kk][cl+1] = nreg.y;
        Ns[kk][cl+2] = nreg.z; Ns[kk][cl+3] = nreg.w;
        __syncthreads();
        if (k0 < 224) {
            wreg = *(const float4*)(wp + k0 + 32 + kl);
            nreg = *(const float4*)(g_nf + (k0 + 32 + kk) * N + n0 + cl);
        }
        #pragma unroll
        for (int k = 0; k < 32; k++) {
            float ev = Ns[k][co];
            acc[0] = fmaf(Ws[ro+0][k], ev, acc[0]);
            acc[1] = fmaf(Ws[ro+1][k], ev, acc[1]);
            acc[2] = fmaf(Ws[ro+2][k], ev, acc[2]);
            acc[3] = fmaf(Ws[ro+3][k], ev, acc[3]);
        }
        __syncthreads();
    }
    #pragma unroll
    for (int q = 0; q < 4; q++) {
        int rq = r0 + ro + q;
        if (rq < 128) out[rq * N + n0 + co] = acc[q];
        else          g_hEo[(rq - 128) * N + n0 + co] = 0.5f * acc[q];
    }
}

// ============================================================
// Kernel 4: edge_out (R5 known-good). grid(576), 256 thr,
// 2 CTAs/SM. CTA tile 64o x 256c, thread 8o x 8c, FFMA2 o-pairs.
// ============================================================
#define EG_ST 260
#define EDGE_SMEM ((64*68 + 64*EG_ST) * 4)

__global__ __launch_bounds__(256, 2) void k_edge(
    const float* __restrict__ edges,
    const float* __restrict__ We,
    float* __restrict__ out)
{
    extern __shared__ float esm[];
    float* Ws = esm;              // [64][68]  Ws[e][o]
    float* Es = esm + 64 * 68;    // [64][260]

    int tid = threadIdx.x, lane = tid & 31, wid = tid >> 5;
    size_t cbase = (size_t)blockIdx.x * 256;

    {
        int o = tid >> 2, e0 = (tid & 3) * 16;
        const float* wp = We + o * 320 + 256 + e0;
        #pragma unroll
        for (int u = 0; u < 16; u += 4) {
            float4 w = *(const float4*)(wp + u);
            Ws[(e0+u+0)*68 + o] = w.x; Ws[(e0+u+1)*68 + o] = w.y;
            Ws[(e0+u+2)*68 + o] = w.z; Ws[(e0+u+3)*68 + o] = w.w;
        }
    }
    #pragma unroll
    for (int it = 0; it < 16; it++) {
        int idx = it * 256 + tid;
        int e = idx >> 6, c4 = idx & 63;
        float4 v = *(const float4*)(edges + (size_t)e * NN + cbase + c4 * 4);
        *(float4*)&Es[e * EG_ST + c4 * 4] = v;
    }
    __syncthreads();

    int o0 = wid * 8;
    int cl = lane * 4;

    unsigned long long acc2[4][8];
    #pragma unroll
    for (int op = 0; op < 4; op++)
        #pragma unroll
        for (int p = 0; p < 8; p++) acc2[op][p] = 0ull;

    #pragma unroll 4
    for (int e = 0; e < 64; e++) {
        const float* wr = Ws + e * 68 + o0;
        F4U w0; w0.f = *(const float4*)wr;
        F4U w1; w1.f = *(const float4*)(wr + 4);
        unsigned long long wd[4] = { w0.u[0], w0.u[1], w1.u[0], w1.u[1] };
        const float* er = Es + e * EG_ST + cl;
        float4 ea = *(const float4*)er;
        float4 eb = *(const float4*)(er + 128);
        float ev[8] = { ea.x, ea.y, ea.z, ea.w, eb.x, eb.y, eb.z, eb.w };
        #pragma unroll
        for (int p = 0; p < 8; p++) {
            unsigned long long evd = pk2(ev[p], ev[p]);
            acc2[0][p] = fma2(wd[0], evd, acc2[0][p]);
            acc2[1][p] = fma2(wd[1], evd, acc2[1][p]);
            acc2[2][p] = fma2(wd[2], evd, acc2[2][p]);
            acc2[3][p] = fma2(wd[3], evd, acc2[3][p]);
        }
    }

    float* ob = out + 128 * N;
    #pragma unroll
    for (int s = 0; s < 2; s++) {
        size_t c = cbase + cl + s * 128;
        int ii = (int)(c / 384), jj = (int)(c % 384);
        #pragma unroll
        for (int op = 0; op < 4; op++) {
            int oA = o0 + 2 * op, oB = oA + 1;
            float eoiA = g_hEo[oA * N + ii];
            float eoiB = g_hEo[oB * N + ii];
            float4 ejA = *(const float4*)(g_hEo + oA * N + jj);
            float4 ejB = *(const float4*)(g_hEo + oB * N + jj);
            float2 v0 = upk(acc2[op][s*4+0]);
            float2 v1 = upk(acc2[op][s*4+1]);
            float2 v2 = upk(acc2[op][s*4+2]);
            float2 v3 = upk(acc2[op][s*4+3]);
            float* pA = ob + (size_t)oA * NN + c;
            float* pB = ob + (size_t)oB * NN + c;
            *(float4*)pA = make_float4(v0.x + eoiA + ejA.x, v1.x + eoiA + ejA.y,
                                       v2.x + eoiA + ejA.z, v3.x + eoiA + ejA.w);
            *(float4*)pB = make_float4(v0.y + eoiB + ejB.x, v1.y + eoiB + ejB.y,
                                       v2.y + eoiB + ejB.z, v3.y + eoiB + ejB.w);
        }
    }
}

// ============================================================
extern "C" void kernel_launch(void* const* d_in, const int* in_sizes, int n_in,
                              void* d_out, int out_size)
{
    const float* nodes = (const float*)d_in[0];
    const float* edges = (const float*)d_in[1];
    const unsigned int* mask = (const unsigned int*)d_in[2];
    const float* Wq = (const float*)d_in[3];
    const float* Wk = (const float*)d_in[4];
    const float* Wv = (const float*)d_in[5];
    const float* Wo = (const float*)d_in[6];
    const float* We = (const float*)d_in[7];
    float* out = (float*)d_out;

    cudaFuncSetAttribute(k_attnA, cudaFuncAttributeMaxDynamicSharedMemorySize, ATTN_SMEM);
    cudaFuncSetAttribute(k_edge, cudaFuncAttributeMaxDynamicSharedMemorySize, EDGE_SMEM);

    k_prep_q<<<dim3(8, 12), 256>>>(nodes, Wq, mask);     // #1
    k_prep_v<<<dim3(8, 12), 256>>>(nodes, Wv);           // #2
    k_qk<<<dim3(48, 8), 256>>>(Wk);                      // #3
    k_attnA<<<768, 256, ATTN_SMEM>>>(edges);             // #4  <- ncu slot
    k_attnB<<<384, 256>>>(Wv);                           // #5
    k_post<<<dim3(6, 12), 256>>>(Wo, We, out);           // #6
    k_edge<<<576, 256, EDGE_SMEM>>>(edges, We, out);     // #7
}